// round 10
// baseline (speedup 1.0000x reference)
#include <cuda_runtime.h>
#include <cuda_fp16.h>
#include <math.h>

#define EDIM 128
#define NH 8
#define NB 2
#define TS 4096
#define HEDIM 1024   // NH*EDIM
#define BT 8192      // NB*TS

// Scratch (device globals; no runtime allocation)
__device__ __half g_Qh[(size_t)BT * HEDIM];
__device__ __half g_Kh[(size_t)BT * HEDIM];
__device__ __half g_Vh[(size_t)BT * HEDIM];
__device__ float  g_Op[(size_t)BT * HEDIM];

// ---------------------------------------------------------------------------
// fp32 GEMM, fp16 epilogue with scale: C = h16(scale * A@B).
// ---------------------------------------------------------------------------
__global__ __launch_bounds__(256) void gemm_h16s(const float* __restrict__ A,
                                                 const float* __restrict__ B,
                                                 __half* __restrict__ C,
                                                 int M, int N, int K,
                                                 float scale) {
    __shared__ float sA[64][33];
    __shared__ float sB[32][64];
    const int tid = threadIdx.x;
    const int tx = tid & 15, ty = tid >> 4;
    const int n0 = blockIdx.x << 6, m0 = blockIdx.y << 6;
    float acc[4][4] = {};
    for (int k0 = 0; k0 < K; k0 += 32) {
#pragma unroll
        for (int i = 0; i < 8; ++i) {
            int idx = tid + (i << 8);
            int r = idx >> 5, c = idx & 31;
            sA[r][c] = A[(size_t)(m0 + r) * K + (k0 + c)];
        }
#pragma unroll
        for (int i = 0; i < 8; ++i) {
            int idx = tid + (i << 8);
            int r = idx >> 6, c = idx & 63;
            sB[r][c] = B[(size_t)(k0 + r) * N + (n0 + c)];
        }
        __syncthreads();
#pragma unroll
        for (int kk = 0; kk < 32; ++kk) {
            float a0 = sA[(ty << 2) + 0][kk];
            float a1 = sA[(ty << 2) + 1][kk];
            float a2 = sA[(ty << 2) + 2][kk];
            float a3 = sA[(ty << 2) + 3][kk];
            float4 b4 = *(const float4*)&sB[kk][tx << 2];
            acc[0][0] += a0 * b4.x; acc[0][1] += a0 * b4.y;
            acc[0][2] += a0 * b4.z; acc[0][3] += a0 * b4.w;
            acc[1][0] += a1 * b4.x; acc[1][1] += a1 * b4.y;
            acc[1][2] += a1 * b4.z; acc[1][3] += a1 * b4.w;
            acc[2][0] += a2 * b4.x; acc[2][1] += a2 * b4.y;
            acc[2][2] += a2 * b4.z; acc[2][3] += a2 * b4.w;
            acc[3][0] += a3 * b4.x; acc[3][1] += a3 * b4.y;
            acc[3][2] += a3 * b4.z; acc[3][3] += a3 * b4.w;
        }
        __syncthreads();
    }
#pragma unroll
    for (int i = 0; i < 4; ++i) {
        size_t base = (size_t)(m0 + (ty << 2) + i) * N + n0 + (tx << 2);
        *(__half2*)&C[base] =
            __floats2half2_rn(acc[i][0] * scale, acc[i][1] * scale);
        *(__half2*)&C[base + 2] =
            __floats2half2_rn(acc[i][2] * scale, acc[i][3] * scale);
    }
}

// fp32 GEMM (final output projection).
__global__ __launch_bounds__(256) void gemm_k(const float* __restrict__ A,
                                              const float* __restrict__ B,
                                              float* __restrict__ C,
                                              int M, int N, int K) {
    __shared__ float sA[64][33];
    __shared__ float sB[32][64];
    const int tid = threadIdx.x;
    const int tx = tid & 15, ty = tid >> 4;
    const int n0 = blockIdx.x << 6, m0 = blockIdx.y << 6;
    float acc[4][4] = {};
    for (int k0 = 0; k0 < K; k0 += 32) {
#pragma unroll
        for (int i = 0; i < 8; ++i) {
            int idx = tid + (i << 8);
            int r = idx >> 5, c = idx & 31;
            sA[r][c] = A[(size_t)(m0 + r) * K + (k0 + c)];
        }
#pragma unroll
        for (int i = 0; i < 8; ++i) {
            int idx = tid + (i << 8);
            int r = idx >> 6, c = idx & 63;
            sB[r][c] = B[(size_t)(k0 + r) * N + (n0 + c)];
        }
        __syncthreads();
#pragma unroll
        for (int kk = 0; kk < 32; ++kk) {
            float a0 = sA[(ty << 2) + 0][kk];
            float a1 = sA[(ty << 2) + 1][kk];
            float a2 = sA[(ty << 2) + 2][kk];
            float a3 = sA[(ty << 2) + 3][kk];
            float4 b4 = *(const float4*)&sB[kk][tx << 2];
            acc[0][0] += a0 * b4.x; acc[0][1] += a0 * b4.y;
            acc[0][2] += a0 * b4.z; acc[0][3] += a0 * b4.w;
            acc[1][0] += a1 * b4.x; acc[1][1] += a1 * b4.y;
            acc[1][2] += a1 * b4.z; acc[1][3] += a1 * b4.w;
            acc[2][0] += a2 * b4.x; acc[2][1] += a2 * b4.y;
            acc[2][2] += a2 * b4.z; acc[2][3] += a2 * b4.w;
            acc[3][0] += a3 * b4.x; acc[3][1] += a3 * b4.y;
            acc[3][2] += a3 * b4.z; acc[3][3] += a3 * b4.w;
        }
        __syncthreads();
    }
#pragma unroll
    for (int i = 0; i < 4; ++i)
#pragma unroll
        for (int j = 0; j < 4; ++j)
            C[(size_t)(m0 + (ty << 2) + i) * N + n0 + (tx << 2) + j] = acc[i][j];
}

// ---------------------------------------------------------------------------
// Flash attention (FA2 layout): 4 warps, each owns 16 full rows.
// Register-P, warp-local softmax. K double-buffered; V single-buffered with
// SPLIT WAITS: S-phase needs only K(n), so V(n) drains during S+softmax.
// 3 CTAs/SM (regs capped at 168, smem 68KB).
// ---------------------------------------------------------------------------
#define BM 64
#define BN 64
#define NT (TS / BN)
#define STRH 136            // halves per row (272B; 272%128==16 -> ldsm ok)
#define STRB 272

#define HOFF_Q  0
#define HOFF_K0 (HOFF_Q  + BM * STRH)   // 8704
#define HOFF_K1 (HOFF_K0 + BN * STRH)   // 17408
#define HOFF_V  (HOFF_K1 + BN * STRH)   // 26112
#define HOFF_END (HOFF_V + BN * STRH)   // 34816
#define SM_BYTES (HOFF_END * 2)         // 69632

#define LDSM4(r0, r1, r2, r3, p)                                              \
    asm volatile("ldmatrix.sync.aligned.m8n8.x4.shared.b16 {%0,%1,%2,%3},[%4];" \
                 : "=r"(r0), "=r"(r1), "=r"(r2), "=r"(r3) : "r"(p))
#define LDSM4T(r0, r1, r2, r3, p)                                             \
    asm volatile("ldmatrix.sync.aligned.m8n8.x4.trans.shared.b16 {%0,%1,%2,%3},[%4];" \
                 : "=r"(r0), "=r"(r1), "=r"(r2), "=r"(r3) : "r"(p))

#define MMA16816(d, a0, a1, a2, a3, b0, b1)                                   \
    asm volatile(                                                             \
        "mma.sync.aligned.m16n8k16.row.col.f32.f16.f16.f32 "                  \
        "{%0,%1,%2,%3},{%4,%5,%6,%7},{%8,%9},{%0,%1,%2,%3};"                  \
        : "+f"(d[0]), "+f"(d[1]), "+f"(d[2]), "+f"(d[3])                      \
        : "r"(a0), "r"(a1), "r"(a2), "r"(a3), "r"(b0), "r"(b1))

#define CPA16(dst, src)                                                       \
    asm volatile("cp.async.cg.shared.global [%0], [%1], 16;" ::               \
                 "r"(dst), "l"(src))
#define CP_COMMIT() asm volatile("cp.async.commit_group;")
#define CP_WAIT2()  asm volatile("cp.async.wait_group 2;")
#define CP_WAIT1()  asm volatile("cp.async.wait_group 1;")
#define CP_WAIT0()  asm volatile("cp.async.wait_group 0;")

__device__ __forceinline__ float ex2f(float x) {
    float r;
    asm("ex2.approx.ftz.f32 %0, %1;" : "=f"(r) : "f"(x));
    return r;
}
__device__ __forceinline__ unsigned packh2(float a, float b) {
    __half2 h = __floats2half2_rn(a, b);
    return *(unsigned*)&h;
}

__global__ __launch_bounds__(128, 3) void flash_attn_fa2(
    const __half* __restrict__ Qg, const __half* __restrict__ Kg,
    const __half* __restrict__ Vg, float* __restrict__ Og) {
    extern __shared__ __align__(16) char smem[];

    const int tid = threadIdx.x;
    const int wid = tid >> 5;       // 0..3, owns rows wid*16..wid*16+15
    const int lane = tid & 31;
    const int g = lane >> 2;        // row-in-8
    const int tg = lane & 3;        // thread-in-group

    const int h = blockIdx.y, b = blockIdx.z;
    const int q0 = blockIdx.x * BM;

    const size_t bh_off = (size_t)b * TS * HEDIM + (size_t)h * EDIM;
    const __half* Qbh = Qg + bh_off;
    const __half* Kbh = Kg + bh_off;
    const __half* Vbh = Vg + bh_off;
    float* Obh = Og + bh_off;

    const unsigned sbase = (unsigned)__cvta_generic_to_shared(smem);
    const unsigned aQ0 = sbase + HOFF_Q * 2 +
        (wid * 16 + (lane & 15)) * STRB + (lane >> 4) * 16;
    const unsigned kpat =
        ((lane & 7) + ((lane >> 4) & 1) * 8) * STRB + ((lane >> 3) & 1) * 16;
    const unsigned vpat =
        ((lane & 7) + ((lane >> 3) & 1) * 8) * STRB + (lane >> 4) * 16;
    const unsigned aK[2] = {sbase + HOFF_K0 * 2 + kpat,
                            sbase + HOFF_K1 * 2 + kpat};
    const unsigned aVb = sbase + HOFF_V * 2 + vpat;
    const unsigned dV = sbase + HOFF_V * 2;

    // ---- group A: Q + K0; group B: V0 ----
    {
        const unsigned dQ = sbase + HOFF_Q * 2;
        const unsigned dK = sbase + HOFF_K0 * 2;
#pragma unroll
        for (int i = 0; i < 8; ++i) {
            int idx = tid + (i << 7);          // 0..1023
            int r = idx >> 4, c = idx & 15;
            const size_t goff = (size_t)r * HEDIM + c * 8;
            const unsigned soff = r * STRB + c * 16;
            CPA16(dQ + soff, Qbh + (size_t)q0 * HEDIM + goff);
            CPA16(dK + soff, Kbh + goff);
        }
        CP_COMMIT();
#pragma unroll
        for (int i = 0; i < 8; ++i) {
            int idx = tid + (i << 7);
            int r = idx >> 4, c = idx & 15;
            CPA16(dV + r * STRB + c * 16, Vbh + (size_t)r * HEDIM + c * 8);
        }
        CP_COMMIT();
    }

    const int row0 = wid * 16 + g;
    const int row1 = row0 + 8;

    float m0 = -INFINITY, m1 = -INFINITY, l0s = 0.f, l1s = 0.f;
    float o[16][4];
#pragma unroll
    for (int nb = 0; nb < 16; ++nb)
#pragma unroll
        for (int j = 0; j < 4; ++j) o[nb][j] = 0.f;

    for (int n = 0; n < NT; ++n) {
        const int buf = n & 1;
        // ---- prefetch K(n+1); wait only for K(n) (V(n) stays in flight) ----
        if (n + 1 < NT) {
            const unsigned dK = sbase + (buf ? HOFF_K0 : HOFF_K1) * 2;
            const size_t kvg = (size_t)(n + 1) * BN * HEDIM;
#pragma unroll
            for (int i = 0; i < 8; ++i) {
                int idx = tid + (i << 7);
                int r = idx >> 4, c = idx & 15;
                CPA16(dK + r * STRB + c * 16, Kbh + kvg + (size_t)r * HEDIM + c * 8);
            }
            CP_COMMIT();
            CP_WAIT2();   // drains K(n); V(n), K(n+1) may remain in flight
        } else {
            CP_WAIT0();
        }
        __syncthreads();  // K(n) visible to all warps

        // ---- S = Q @ K^T over full 64 cols (Q frags reloaded per ks) ----
        float s[8][4];
#pragma unroll
        for (int nb = 0; nb < 8; ++nb)
#pragma unroll
            for (int j = 0; j < 4; ++j) s[nb][j] = 0.f;

        unsigned ak = aK[buf];
#pragma unroll
        for (int ks = 0; ks < 8; ++ks) {
            unsigned q0r, q1r, q2r, q3r;
            LDSM4(q0r, q1r, q2r, q3r, aQ0 + ks * 32);
#pragma unroll
            for (int nb2 = 0; nb2 < 4; ++nb2) {
                unsigned b0, b1, b2, b3;
                LDSM4(b0, b1, b2, b3, ak + nb2 * 16 * STRB);
                MMA16816(s[nb2 * 2 + 0], q0r, q1r, q2r, q3r, b0, b1);
                MMA16816(s[nb2 * 2 + 1], q0r, q1r, q2r, q3r, b2, b3);
            }
            ak += 32;
        }

        // ---- warp-local online softmax (base-2; scale folded upstream) ----
        float mx0 = -INFINITY, mx1 = -INFINITY;
#pragma unroll
        for (int nb = 0; nb < 8; ++nb) {
            mx0 = fmaxf(mx0, fmaxf(s[nb][0], s[nb][1]));
            mx1 = fmaxf(mx1, fmaxf(s[nb][2], s[nb][3]));
        }
        mx0 = fmaxf(mx0, __shfl_xor_sync(0xffffffffu, mx0, 1));
        mx0 = fmaxf(mx0, __shfl_xor_sync(0xffffffffu, mx0, 2));
        mx1 = fmaxf(mx1, __shfl_xor_sync(0xffffffffu, mx1, 1));
        mx1 = fmaxf(mx1, __shfl_xor_sync(0xffffffffu, mx1, 2));
        const float mn0 = fmaxf(m0, mx0), mn1 = fmaxf(m1, mx1);
        const float al0 = ex2f(m0 - mn0), al1 = ex2f(m1 - mn1);
        m0 = mn0; m1 = mn1;

        float ps0 = 0.f, ps1 = 0.f;
        unsigned ph[8][2];
#pragma unroll
        for (int nb = 0; nb < 8; ++nb) {
            s[nb][0] = ex2f(s[nb][0] - mn0);
            s[nb][1] = ex2f(s[nb][1] - mn0);
            s[nb][2] = ex2f(s[nb][2] - mn1);
            s[nb][3] = ex2f(s[nb][3] - mn1);
            ps0 += s[nb][0] + s[nb][1];
            ps1 += s[nb][2] + s[nb][3];
            ph[nb][0] = packh2(s[nb][0], s[nb][1]);   // row g
            ph[nb][1] = packh2(s[nb][2], s[nb][3]);   // row g+8
        }
        ps0 += __shfl_xor_sync(0xffffffffu, ps0, 1);
        ps0 += __shfl_xor_sync(0xffffffffu, ps0, 2);
        ps1 += __shfl_xor_sync(0xffffffffu, ps1, 1);
        ps1 += __shfl_xor_sync(0xffffffffu, ps1, 2);
        l0s = l0s * al0 + ps0;
        l1s = l1s * al1 + ps1;

        // rescale O only if some row max actually moved (al==1.0 is exact)
        if (__any_sync(0xffffffffu, (al0 != 1.f) || (al1 != 1.f))) {
#pragma unroll
            for (int nb = 0; nb < 16; ++nb) {
                o[nb][0] *= al0; o[nb][1] *= al0;
                o[nb][2] *= al1; o[nb][3] *= al1;
            }
        }

        // ---- now require V(n); it drained during S+softmax ----
        CP_WAIT1();       // V(n) done (K(n+1) may remain in flight)
        __syncthreads();  // V(n) visible to all warps

        // ---- O += P @ V (P from registers; full 128 cols) ----
        unsigned av0 = aVb;
#pragma unroll
        for (int ks = 0; ks < 4; ++ks) {
            const unsigned pa0 = ph[2 * ks][0], pa1 = ph[2 * ks][1];
            const unsigned pa2 = ph[2 * ks + 1][0], pa3 = ph[2 * ks + 1][1];
            unsigned av = av0;
#pragma unroll
            for (int np = 0; np < 8; ++np) {
                unsigned v0, v1, v2, v3;
                LDSM4T(v0, v1, v2, v3, av);
                MMA16816(o[np * 2 + 0], pa0, pa1, pa2, pa3, v0, v1);
                MMA16816(o[np * 2 + 1], pa0, pa1, pa2, pa3, v2, v3);
                av += 32;
            }
            av0 += 16 * STRB;
        }
        __syncthreads();  // all warps done with V(n) before overwrite

        // ---- prefetch V(n+1) into the (single) V buffer ----
        if (n + 1 < NT) {
            const size_t kvg = (size_t)(n + 1) * BN * HEDIM;
#pragma unroll
            for (int i = 0; i < 8; ++i) {
                int idx = tid + (i << 7);
                int r = idx >> 4, c = idx & 15;
                CPA16(dV + r * STRB + c * 16, Vbh + kvg + (size_t)r * HEDIM + c * 8);
            }
            CP_COMMIT();
        }
    }

    // ---- normalize + write O ----
    const float inv0 = 1.f / l0s, inv1 = 1.f / l1s;
#pragma unroll
    for (int nb = 0; nb < 16; ++nb) {
        const int col = nb * 8 + 2 * tg;
        float2 r0v = make_float2(o[nb][0] * inv0, o[nb][1] * inv0);
        float2 r1v = make_float2(o[nb][2] * inv1, o[nb][3] * inv1);
        *(float2*)&Obh[(size_t)(q0 + row0) * HEDIM + col] = r0v;
        *(float2*)&Obh[(size_t)(q0 + row1) * HEDIM + col] = r1v;
    }
}

// ---------------------------------------------------------------------------
extern "C" void kernel_launch(void* const* d_in, const int* in_sizes, int n_in,
                              void* d_out, int out_size) {
    (void)in_sizes; (void)n_in; (void)out_size;
    const float* k  = (const float*)d_in[0];
    const float* q  = (const float*)d_in[1];
    const float* v  = (const float*)d_in[2];
    const float* Wk = (const float*)d_in[3];
    const float* Wq = (const float*)d_in[4];
    const float* Wv = (const float*)d_in[5];
    const float* Wu = (const float*)d_in[6];
    float* out = (float*)d_out;

    __half *gQ, *gK, *gV;
    float* gO;
    cudaGetSymbolAddress((void**)&gQ, g_Qh);
    cudaGetSymbolAddress((void**)&gK, g_Kh);
    cudaGetSymbolAddress((void**)&gV, g_Vh);
    cudaGetSymbolAddress((void**)&gO, g_Op);

    cudaFuncSetAttribute(flash_attn_fa2,
                         cudaFuncAttributeMaxDynamicSharedMemorySize, SM_BYTES);

    // log2(e)/sqrt(128) folded into Q projection (softmax runs in base 2)
    const float qscale = 0.12751744f;
    dim3 blk(256);
    dim3 gproj(HEDIM / 64, BT / 64);
    gemm_h16s<<<gproj, blk>>>(q, Wq, gQ, BT, HEDIM, EDIM, qscale);
    gemm_h16s<<<gproj, blk>>>(k, Wk, gK, BT, HEDIM, EDIM, 1.0f);
    gemm_h16s<<<gproj, blk>>>(v, Wv, gV, BT, HEDIM, EDIM, 1.0f);

    dim3 gatt(TS / BM, NH, NB);
    flash_attn_fa2<<<gatt, dim3(128), SM_BYTES>>>(gQ, gK, gV, gO);

    dim3 gout(EDIM / 64, BT / 64);
    gemm_k<<<gout, blk>>>(gO, Wu, out, BT, EDIM, HEDIM);
}

// round 11
// speedup vs baseline: 1.3356x; 1.3356x over previous
#include <cuda_runtime.h>
#include <cuda_fp16.h>
#include <math.h>

#define EDIM 128
#define NH 8
#define NB 2
#define TS 4096
#define HEDIM 1024   // NH*EDIM
#define BT 8192      // NB*TS

// Scratch (device globals; no runtime allocation)
__device__ __half g_Qh[(size_t)BT * HEDIM];
__device__ __half g_Kh[(size_t)BT * HEDIM];
__device__ __half g_Vh[(size_t)BT * HEDIM];
__device__ float  g_Op[(size_t)BT * HEDIM];

// ---------------------------------------------------------------------------
// Shared mma/ldmatrix macros
// ---------------------------------------------------------------------------
#define LDSM4(r0, r1, r2, r3, p)                                              \
    asm volatile("ldmatrix.sync.aligned.m8n8.x4.shared.b16 {%0,%1,%2,%3},[%4];" \
                 : "=r"(r0), "=r"(r1), "=r"(r2), "=r"(r3) : "r"(p))
#define LDSM4T(r0, r1, r2, r3, p)                                             \
    asm volatile("ldmatrix.sync.aligned.m8n8.x4.trans.shared.b16 {%0,%1,%2,%3},[%4];" \
                 : "=r"(r0), "=r"(r1), "=r"(r2), "=r"(r3) : "r"(p))
#define MMA16816(d, a0, a1, a2, a3, b0, b1)                                   \
    asm volatile(                                                             \
        "mma.sync.aligned.m16n8k16.row.col.f32.f16.f16.f32 "                  \
        "{%0,%1,%2,%3},{%4,%5,%6,%7},{%8,%9},{%0,%1,%2,%3};"                  \
        : "+f"(d[0]), "+f"(d[1]), "+f"(d[2]), "+f"(d[3])                      \
        : "r"(a0), "r"(a1), "r"(a2), "r"(a3), "r"(b0), "r"(b1))
#define CPA16(dst, src)                                                       \
    asm volatile("cp.async.cg.shared.global [%0], [%1], 16;" ::               \
                 "r"(dst), "l"(src))
#define CP_COMMIT() asm volatile("cp.async.commit_group;")
#define CP_WAIT1()  asm volatile("cp.async.wait_group 1;")
#define CP_WAIT0()  asm volatile("cp.async.wait_group 0;")

__device__ __forceinline__ float ex2f(float x) {
    float r;
    asm("ex2.approx.ftz.f32 %0, %1;" : "=f"(r) : "f"(x));
    return r;
}
__device__ __forceinline__ unsigned packh2(float a, float b) {
    __half2 h = __floats2half2_rn(a, b);
    return *(unsigned*)&h;
}

// ---------------------------------------------------------------------------
// Projection GEMM on fp16 tensor cores:
// C_h16[M,1024] = h16(scale * A_f32[M,128] @ B_f32[128,1024]).
// CTA = 128x128 tile, single K=128 pass. 8 warps = 4 m-strips(32) x 2 n(64).
// ---------------------------------------------------------------------------
#define GP_STRB 272                       // 128 halves + 16B pad
#define GP_SB_OFF (128 * GP_STRB)         // B tile after A tile
#define GP_SMEM (2 * 128 * GP_STRB)       // 69632 bytes

__global__ __launch_bounds__(256, 2) void gemm_proj(
    const float* __restrict__ A, const float* __restrict__ B,
    __half* __restrict__ C, float scale) {
    extern __shared__ __align__(16) char smem[];
    const int tid = threadIdx.x;
    const int wid = tid >> 5;
    const int lane = tid & 31;
    const int g = lane >> 2, tg = lane & 3;
    const int wm = wid & 3;      // m-strip (32 rows)
    const int wn = wid >> 2;     // n-half (64 cols)
    const int n0 = blockIdx.x << 7, m0 = blockIdx.y << 7;

    // stage A,B tiles as fp16 (convert on the fly)
#pragma unroll
    for (int i = 0; i < 16; ++i) {
        int idx = tid + (i << 8);          // 0..4095
        int r = idx >> 5, c4 = idx & 31;   // row, float4-chunk
        float4 a = *(const float4*)&A[(size_t)(m0 + r) * EDIM + c4 * 4];
        float4 bv = *(const float4*)&B[(size_t)r * HEDIM + n0 + c4 * 4];
        *(unsigned*)(smem + r * GP_STRB + c4 * 8) = packh2(a.x, a.y);
        *(unsigned*)(smem + r * GP_STRB + c4 * 8 + 4) = packh2(a.z, a.w);
        *(unsigned*)(smem + GP_SB_OFF + r * GP_STRB + c4 * 8) = packh2(bv.x, bv.y);
        *(unsigned*)(smem + GP_SB_OFF + r * GP_STRB + c4 * 8 + 4) = packh2(bv.z, bv.w);
    }
    __syncthreads();

    const unsigned sbase = (unsigned)__cvta_generic_to_shared(smem);
    const unsigned aA0 = sbase + (wm * 32 + (lane & 15)) * GP_STRB + (lane >> 4) * 16;
    const unsigned aB0 = sbase + GP_SB_OFF +
        ((lane & 7) + ((lane >> 3) & 1) * 8) * GP_STRB + wn * 128 + (lane >> 4) * 16;

    float acc[16][4];
#pragma unroll
    for (int i = 0; i < 16; ++i)
#pragma unroll
        for (int j = 0; j < 4; ++j) acc[i][j] = 0.f;

#pragma unroll
    for (int ks = 0; ks < 8; ++ks) {
        unsigned aq[2][4];
#pragma unroll
        for (int mb = 0; mb < 2; ++mb)
            LDSM4(aq[mb][0], aq[mb][1], aq[mb][2], aq[mb][3],
                  aA0 + mb * 16 * GP_STRB + ks * 32);
        unsigned av = aB0 + ks * 16 * GP_STRB;
#pragma unroll
        for (int np = 0; np < 4; ++np) {
            unsigned v0, v1, v2, v3;
            LDSM4T(v0, v1, v2, v3, av);
            av += 32;
#pragma unroll
            for (int mb = 0; mb < 2; ++mb) {
                MMA16816(acc[mb * 8 + np * 2 + 0],
                         aq[mb][0], aq[mb][1], aq[mb][2], aq[mb][3], v0, v1);
                MMA16816(acc[mb * 8 + np * 2 + 1],
                         aq[mb][0], aq[mb][1], aq[mb][2], aq[mb][3], v2, v3);
            }
        }
    }

    // epilogue: fp16 with scale
#pragma unroll
    for (int mb = 0; mb < 2; ++mb) {
        const int r0 = m0 + wm * 32 + mb * 16 + g;
        const int r1 = r0 + 8;
#pragma unroll
        for (int nb = 0; nb < 8; ++nb) {
            const int a = mb * 8 + nb;
            const int col = n0 + wn * 64 + nb * 8 + 2 * tg;
            *(__half2*)&C[(size_t)r0 * HEDIM + col] =
                __floats2half2_rn(acc[a][0] * scale, acc[a][1] * scale);
            *(__half2*)&C[(size_t)r1 * HEDIM + col] =
                __floats2half2_rn(acc[a][2] * scale, acc[a][3] * scale);
        }
    }
}

// ---------------------------------------------------------------------------
// fp32 GEMM (final output projection): C[M,N] = A[M,K] @ B[K,N].
// ---------------------------------------------------------------------------
__global__ __launch_bounds__(256) void gemm_k(const float* __restrict__ A,
                                              const float* __restrict__ B,
                                              float* __restrict__ C,
                                              int M, int N, int K) {
    __shared__ float sA[64][33];
    __shared__ float sB[32][64];
    const int tid = threadIdx.x;
    const int tx = tid & 15, ty = tid >> 4;
    const int n0 = blockIdx.x << 6, m0 = blockIdx.y << 6;
    float acc[4][4] = {};
    for (int k0 = 0; k0 < K; k0 += 32) {
#pragma unroll
        for (int i = 0; i < 8; ++i) {
            int idx = tid + (i << 8);
            int r = idx >> 5, c = idx & 31;
            sA[r][c] = A[(size_t)(m0 + r) * K + (k0 + c)];
        }
#pragma unroll
        for (int i = 0; i < 8; ++i) {
            int idx = tid + (i << 8);
            int r = idx >> 6, c = idx & 63;
            sB[r][c] = B[(size_t)(k0 + r) * N + (n0 + c)];
        }
        __syncthreads();
#pragma unroll
        for (int kk = 0; kk < 32; ++kk) {
            float a0 = sA[(ty << 2) + 0][kk];
            float a1 = sA[(ty << 2) + 1][kk];
            float a2 = sA[(ty << 2) + 2][kk];
            float a3 = sA[(ty << 2) + 3][kk];
            float4 b4 = *(const float4*)&sB[kk][tx << 2];
            acc[0][0] += a0 * b4.x; acc[0][1] += a0 * b4.y;
            acc[0][2] += a0 * b4.z; acc[0][3] += a0 * b4.w;
            acc[1][0] += a1 * b4.x; acc[1][1] += a1 * b4.y;
            acc[1][2] += a1 * b4.z; acc[1][3] += a1 * b4.w;
            acc[2][0] += a2 * b4.x; acc[2][1] += a2 * b4.y;
            acc[2][2] += a2 * b4.z; acc[2][3] += a2 * b4.w;
            acc[3][0] += a3 * b4.x; acc[3][1] += a3 * b4.y;
            acc[3][2] += a3 * b4.z; acc[3][3] += a3 * b4.w;
        }
        __syncthreads();
    }
#pragma unroll
    for (int i = 0; i < 4; ++i)
#pragma unroll
        for (int j = 0; j < 4; ++j)
            C[(size_t)(m0 + (ty << 2) + i) * N + n0 + (tx << 2) + j] = acc[i][j];
}

// ---------------------------------------------------------------------------
// Flash attention (R8 config — best known): FA2 layout, 4 warps x 16 full
// rows, register-P, warp-local softmax, K AND V double-buffered, persistent
// Q fragments, 2 CTAs/SM.
// ---------------------------------------------------------------------------
#define BM 64
#define BN 64
#define NT (TS / BN)
#define STRH 136            // halves per row (272B; 272%128==16 -> ldsm ok)
#define STRB 272

#define HOFF_Q  0
#define HOFF_K0 (HOFF_Q  + BM * STRH)   // 8704
#define HOFF_V0 (HOFF_K0 + BN * STRH)   // 17408
#define HOFF_K1 (HOFF_V0 + BN * STRH)   // 26112
#define HOFF_V1 (HOFF_K1 + BN * STRH)   // 34816
#define HOFF_END (HOFF_V1 + BN * STRH)  // 43520
#define SM_BYTES (HOFF_END * 2)         // 87040

__global__ __launch_bounds__(128, 2) void flash_attn_fa2(
    const __half* __restrict__ Qg, const __half* __restrict__ Kg,
    const __half* __restrict__ Vg, float* __restrict__ Og) {
    extern __shared__ __align__(16) char smem[];

    const int tid = threadIdx.x;
    const int wid = tid >> 5;       // 0..3, owns rows wid*16..wid*16+15
    const int lane = tid & 31;
    const int g = lane >> 2;        // row-in-8
    const int tg = lane & 3;        // thread-in-group

    const int h = blockIdx.y, b = blockIdx.z;
    const int q0 = blockIdx.x * BM;

    const size_t bh_off = (size_t)b * TS * HEDIM + (size_t)h * EDIM;
    const __half* Qbh = Qg + bh_off;
    const __half* Kbh = Kg + bh_off;
    const __half* Vbh = Vg + bh_off;
    float* Obh = Og + bh_off;

    const unsigned sbase = (unsigned)__cvta_generic_to_shared(smem);
    const unsigned aQ0 = sbase + HOFF_Q * 2 +
        (wid * 16 + (lane & 15)) * STRB + (lane >> 4) * 16;
    const unsigned kpat =
        ((lane & 7) + ((lane >> 4) & 1) * 8) * STRB + ((lane >> 3) & 1) * 16;
    const unsigned vpat =
        ((lane & 7) + ((lane >> 3) & 1) * 8) * STRB + (lane >> 4) * 16;
    const unsigned aK[2] = {sbase + HOFF_K0 * 2 + kpat,
                            sbase + HOFF_K1 * 2 + kpat};
    const unsigned aV[2] = {sbase + HOFF_V0 * 2 + vpat,
                            sbase + HOFF_V1 * 2 + vpat};

    // ---- group 0: Q tile + KV tile 0 ----
    {
        const unsigned dQ = sbase + HOFF_Q * 2;
        const unsigned dK = sbase + HOFF_K0 * 2;
        const unsigned dV = sbase + HOFF_V0 * 2;
#pragma unroll
        for (int i = 0; i < 8; ++i) {
            int idx = tid + (i << 7);          // 0..1023
            int r = idx >> 4, c = idx & 15;
            const size_t goff = (size_t)r * HEDIM + c * 8;
            const unsigned soff = r * STRB + c * 16;
            CPA16(dQ + soff, Qbh + (size_t)q0 * HEDIM + goff);
            CPA16(dK + soff, Kbh + goff);
            CPA16(dV + soff, Vbh + goff);
        }
        CP_COMMIT();
    }

    const int row0 = wid * 16 + g;
    const int row1 = row0 + 8;

    float m0 = -INFINITY, m1 = -INFINITY, l0s = 0.f, l1s = 0.f;
    float o[16][4];
#pragma unroll
    for (int nb = 0; nb < 16; ++nb)
#pragma unroll
        for (int j = 0; j < 4; ++j) o[nb][j] = 0.f;

    unsigned qf[8][4];  // persistent Q fragments (k = 0..127)

    for (int n = 0; n < NT; ++n) {
        const int buf = n & 1;
        // ---- prefetch KV tile n+1 into the other buffer ----
        if (n + 1 < NT) {
            const unsigned dK = sbase + (buf ? HOFF_K0 : HOFF_K1) * 2;
            const unsigned dV = sbase + (buf ? HOFF_V0 : HOFF_V1) * 2;
            const size_t kvg = (size_t)(n + 1) * BN * HEDIM;
#pragma unroll
            for (int i = 0; i < 8; ++i) {
                int idx = tid + (i << 7);
                int r = idx >> 4, c = idx & 15;
                const size_t goff = kvg + (size_t)r * HEDIM + c * 8;
                const unsigned soff = r * STRB + c * 16;
                CPA16(dK + soff, Kbh + goff);
                CPA16(dV + soff, Vbh + goff);
            }
            CP_COMMIT();
            CP_WAIT1();   // tile n's group done
        } else {
            CP_WAIT0();
        }
        __syncthreads();  // all threads' copies of tile n visible

        if (n == 0) {     // preload Q fragments once
#pragma unroll
            for (int ks = 0; ks < 8; ++ks)
                LDSM4(qf[ks][0], qf[ks][1], qf[ks][2], qf[ks][3],
                      aQ0 + ks * 32);
        }

        // ---- S = Q @ K^T over full 64 cols ----
        float s[8][4];
#pragma unroll
        for (int nb = 0; nb < 8; ++nb)
#pragma unroll
            for (int j = 0; j < 4; ++j) s[nb][j] = 0.f;

        unsigned ak = aK[buf];
#pragma unroll
        for (int ks = 0; ks < 8; ++ks) {
#pragma unroll
            for (int nb2 = 0; nb2 < 4; ++nb2) {
                unsigned b0, b1, b2, b3;
                LDSM4(b0, b1, b2, b3, ak + nb2 * 16 * STRB);
                MMA16816(s[nb2 * 2 + 0], qf[ks][0], qf[ks][1], qf[ks][2],
                         qf[ks][3], b0, b1);
                MMA16816(s[nb2 * 2 + 1], qf[ks][0], qf[ks][1], qf[ks][2],
                         qf[ks][3], b2, b3);
            }
            ak += 32;
        }

        // ---- warp-local online softmax (base-2; scale folded upstream) ----
        float mx0 = -INFINITY, mx1 = -INFINITY;
#pragma unroll
        for (int nb = 0; nb < 8; ++nb) {
            mx0 = fmaxf(mx0, fmaxf(s[nb][0], s[nb][1]));
            mx1 = fmaxf(mx1, fmaxf(s[nb][2], s[nb][3]));
        }
        mx0 = fmaxf(mx0, __shfl_xor_sync(0xffffffffu, mx0, 1));
        mx0 = fmaxf(mx0, __shfl_xor_sync(0xffffffffu, mx0, 2));
        mx1 = fmaxf(mx1, __shfl_xor_sync(0xffffffffu, mx1, 1));
        mx1 = fmaxf(mx1, __shfl_xor_sync(0xffffffffu, mx1, 2));
        const float mn0 = fmaxf(m0, mx0), mn1 = fmaxf(m1, mx1);
        const float al0 = ex2f(m0 - mn0), al1 = ex2f(m1 - mn1);
        m0 = mn0; m1 = mn1;

        float ps0 = 0.f, ps1 = 0.f;
        unsigned ph[8][2];
#pragma unroll
        for (int nb = 0; nb < 8; ++nb) {
            s[nb][0] = ex2f(s[nb][0] - mn0);
            s[nb][1] = ex2f(s[nb][1] - mn0);
            s[nb][2] = ex2f(s[nb][2] - mn1);
            s[nb][3] = ex2f(s[nb][3] - mn1);
            ps0 += s[nb][0] + s[nb][1];
            ps1 += s[nb][2] + s[nb][3];
            ph[nb][0] = packh2(s[nb][0], s[nb][1]);   // row g
            ph[nb][1] = packh2(s[nb][2], s[nb][3]);   // row g+8
        }
        ps0 += __shfl_xor_sync(0xffffffffu, ps0, 1);
        ps0 += __shfl_xor_sync(0xffffffffu, ps0, 2);
        ps1 += __shfl_xor_sync(0xffffffffu, ps1, 1);
        ps1 += __shfl_xor_sync(0xffffffffu, ps1, 2);
        l0s = l0s * al0 + ps0;
        l1s = l1s * al1 + ps1;

        // rescale O
#pragma unroll
        for (int nb = 0; nb < 16; ++nb) {
            o[nb][0] *= al0; o[nb][1] *= al0;
            o[nb][2] *= al1; o[nb][3] *= al1;
        }

        // ---- O += P @ V (P from registers; full 128 cols) ----
        unsigned av0 = aV[buf];
#pragma unroll
        for (int ks = 0; ks < 4; ++ks) {
            const unsigned pa0 = ph[2 * ks][0], pa1 = ph[2 * ks][1];
            const unsigned pa2 = ph[2 * ks + 1][0], pa3 = ph[2 * ks + 1][1];
            unsigned av = av0;
#pragma unroll
            for (int np = 0; np < 8; ++np) {
                unsigned v0, v1, v2, v3;
                LDSM4T(v0, v1, v2, v3, av);
                MMA16816(o[np * 2 + 0], pa0, pa1, pa2, pa3, v0, v1);
                MMA16816(o[np * 2 + 1], pa0, pa1, pa2, pa3, v2, v3);
                av += 32;
            }
            av0 += 16 * STRB;
        }
        __syncthreads();  // all warps done reading this buf before overwrite
    }

    // ---- normalize + write O ----
    const float inv0 = 1.f / l0s, inv1 = 1.f / l1s;
#pragma unroll
    for (int nb = 0; nb < 16; ++nb) {
        const int col = nb * 8 + 2 * tg;
        float2 r0v = make_float2(o[nb][0] * inv0, o[nb][1] * inv0);
        float2 r1v = make_float2(o[nb][2] * inv1, o[nb][3] * inv1);
        *(float2*)&Obh[(size_t)(q0 + row0) * HEDIM + col] = r0v;
        *(float2*)&Obh[(size_t)(q0 + row1) * HEDIM + col] = r1v;
    }
}

// ---------------------------------------------------------------------------
extern "C" void kernel_launch(void* const* d_in, const int* in_sizes, int n_in,
                              void* d_out, int out_size) {
    (void)in_sizes; (void)n_in; (void)out_size;
    const float* k  = (const float*)d_in[0];
    const float* q  = (const float*)d_in[1];
    const float* v  = (const float*)d_in[2];
    const float* Wk = (const float*)d_in[3];
    const float* Wq = (const float*)d_in[4];
    const float* Wv = (const float*)d_in[5];
    const float* Wu = (const float*)d_in[6];
    float* out = (float*)d_out;

    __half *gQ, *gK, *gV;
    float* gO;
    cudaGetSymbolAddress((void**)&gQ, g_Qh);
    cudaGetSymbolAddress((void**)&gK, g_Kh);
    cudaGetSymbolAddress((void**)&gV, g_Vh);
    cudaGetSymbolAddress((void**)&gO, g_Op);

    cudaFuncSetAttribute(flash_attn_fa2,
                         cudaFuncAttributeMaxDynamicSharedMemorySize, SM_BYTES);
    cudaFuncSetAttribute(gemm_proj,
                         cudaFuncAttributeMaxDynamicSharedMemorySize, GP_SMEM);

    // log2(e)/sqrt(128) folded into Q projection (softmax runs in base 2)
    const float qscale = 0.12751744f;
    dim3 blk(256);
    dim3 gproj(HEDIM / 128, BT / 128);   // 8 x 64
    gemm_proj<<<gproj, blk, GP_SMEM>>>(q, Wq, gQ, qscale);
    gemm_proj<<<gproj, blk, GP_SMEM>>>(k, Wk, gK, 1.0f);
    gemm_proj<<<gproj, blk, GP_SMEM>>>(v, Wv, gV, 1.0f);

    dim3 gatt(TS / BM, NH, NB);
    flash_attn_fa2<<<gatt, dim3(128), SM_BYTES>>>(gQ, gK, gV, gO);

    dim3 gout(EDIM / 64, BT / 64);
    gemm_k<<<gout, blk>>>(gO, Wu, out, BT, EDIM, HEDIM);
}

// round 12
// speedup vs baseline: 1.4513x; 1.0867x over previous
#include <cuda_runtime.h>
#include <cuda_fp16.h>
#include <math.h>

#define EDIM 128
#define NH 8
#define NB 2
#define TS 4096
#define HEDIM 1024   // NH*EDIM
#define BT 8192      // NB*TS

// Scratch (device globals; no runtime allocation)
__device__ __half g_Qh[(size_t)BT * HEDIM];
__device__ __half g_Kh[(size_t)BT * HEDIM];
__device__ __half g_Vh[(size_t)BT * HEDIM];
__device__ __half g_Oh[(size_t)BT * HEDIM];
__device__ __half g_Wuh[(size_t)HEDIM * EDIM];

// ---------------------------------------------------------------------------
// Shared mma/ldmatrix macros
// ---------------------------------------------------------------------------
#define LDSM4(r0, r1, r2, r3, p)                                              \
    asm volatile("ldmatrix.sync.aligned.m8n8.x4.shared.b16 {%0,%1,%2,%3},[%4];" \
                 : "=r"(r0), "=r"(r1), "=r"(r2), "=r"(r3) : "r"(p))
#define LDSM4T(r0, r1, r2, r3, p)                                             \
    asm volatile("ldmatrix.sync.aligned.m8n8.x4.trans.shared.b16 {%0,%1,%2,%3},[%4];" \
                 : "=r"(r0), "=r"(r1), "=r"(r2), "=r"(r3) : "r"(p))
#define MMA16816(d, a0, a1, a2, a3, b0, b1)                                   \
    asm volatile(                                                             \
        "mma.sync.aligned.m16n8k16.row.col.f32.f16.f16.f32 "                  \
        "{%0,%1,%2,%3},{%4,%5,%6,%7},{%8,%9},{%0,%1,%2,%3};"                  \
        : "+f"(d[0]), "+f"(d[1]), "+f"(d[2]), "+f"(d[3])                      \
        : "r"(a0), "r"(a1), "r"(a2), "r"(a3), "r"(b0), "r"(b1))
#define CPA16(dst, src)                                                       \
    asm volatile("cp.async.cg.shared.global [%0], [%1], 16;" ::               \
                 "r"(dst), "l"(src))
#define CP_COMMIT() asm volatile("cp.async.commit_group;")
#define CP_WAIT1()  asm volatile("cp.async.wait_group 1;")
#define CP_WAIT0()  asm volatile("cp.async.wait_group 0;")

__device__ __forceinline__ float ex2f(float x) {
    float r;
    asm("ex2.approx.ftz.f32 %0, %1;" : "=f"(r) : "f"(x));
    return r;
}
__device__ __forceinline__ unsigned packh2(float a, float b) {
    __half2 h = __floats2half2_rn(a, b);
    return *(unsigned*)&h;
}

// ---------------------------------------------------------------------------
// Wu fp32 -> fp16 (one-time convert)
// ---------------------------------------------------------------------------
__global__ __launch_bounds__(256) void wu_to_h(const float* __restrict__ W,
                                               __half* __restrict__ Wh) {
    int idx = (blockIdx.x * 256 + threadIdx.x) * 4;
    float4 v = *(const float4*)&W[idx];
    *(unsigned*)&Wh[idx] = packh2(v.x, v.y);
    *(unsigned*)&Wh[idx + 2] = packh2(v.z, v.w);
}

// ---------------------------------------------------------------------------
// Projection GEMM on fp16 tensor cores:
// C_h16[M,1024] = h16(scale * A_f32[M,128] @ B_f32[128,1024]).
// CTA = 128x128 tile, single K=128 pass. 8 warps = 4 m-strips(32) x 2 n(64).
// ---------------------------------------------------------------------------
#define GP_STRB 272
#define GP_SB_OFF (128 * GP_STRB)
#define GP_SMEM (2 * 128 * GP_STRB)       // 69632 bytes

__global__ __launch_bounds__(256, 2) void gemm_proj(
    const float* __restrict__ A, const float* __restrict__ B,
    __half* __restrict__ C, float scale) {
    extern __shared__ __align__(16) char smem[];
    const int tid = threadIdx.x;
    const int wid = tid >> 5;
    const int lane = tid & 31;
    const int g = lane >> 2, tg = lane & 3;
    const int wm = wid & 3;
    const int wn = wid >> 2;
    const int n0 = blockIdx.x << 7, m0 = blockIdx.y << 7;

#pragma unroll
    for (int i = 0; i < 16; ++i) {
        int idx = tid + (i << 8);
        int r = idx >> 5, c4 = idx & 31;
        float4 a = *(const float4*)&A[(size_t)(m0 + r) * EDIM + c4 * 4];
        float4 bv = *(const float4*)&B[(size_t)r * HEDIM + n0 + c4 * 4];
        *(unsigned*)(smem + r * GP_STRB + c4 * 8) = packh2(a.x, a.y);
        *(unsigned*)(smem + r * GP_STRB + c4 * 8 + 4) = packh2(a.z, a.w);
        *(unsigned*)(smem + GP_SB_OFF + r * GP_STRB + c4 * 8) = packh2(bv.x, bv.y);
        *(unsigned*)(smem + GP_SB_OFF + r * GP_STRB + c4 * 8 + 4) = packh2(bv.z, bv.w);
    }
    __syncthreads();

    const unsigned sbase = (unsigned)__cvta_generic_to_shared(smem);
    const unsigned aA0 = sbase + (wm * 32 + (lane & 15)) * GP_STRB + (lane >> 4) * 16;
    const unsigned aB0 = sbase + GP_SB_OFF +
        ((lane & 7) + ((lane >> 3) & 1) * 8) * GP_STRB + wn * 128 + (lane >> 4) * 16;

    float acc[16][4];
#pragma unroll
    for (int i = 0; i < 16; ++i)
#pragma unroll
        for (int j = 0; j < 4; ++j) acc[i][j] = 0.f;

#pragma unroll
    for (int ks = 0; ks < 8; ++ks) {
        unsigned aq[2][4];
#pragma unroll
        for (int mb = 0; mb < 2; ++mb)
            LDSM4(aq[mb][0], aq[mb][1], aq[mb][2], aq[mb][3],
                  aA0 + mb * 16 * GP_STRB + ks * 32);
        unsigned av = aB0 + ks * 16 * GP_STRB;
#pragma unroll
        for (int np = 0; np < 4; ++np) {
            unsigned v0, v1, v2, v3;
            LDSM4T(v0, v1, v2, v3, av);
            av += 32;
#pragma unroll
            for (int mb = 0; mb < 2; ++mb) {
                MMA16816(acc[mb * 8 + np * 2 + 0],
                         aq[mb][0], aq[mb][1], aq[mb][2], aq[mb][3], v0, v1);
                MMA16816(acc[mb * 8 + np * 2 + 1],
                         aq[mb][0], aq[mb][1], aq[mb][2], aq[mb][3], v2, v3);
            }
        }
    }

#pragma unroll
    for (int mb = 0; mb < 2; ++mb) {
        const int r0 = m0 + wm * 32 + mb * 16 + g;
        const int r1 = r0 + 8;
#pragma unroll
        for (int nb = 0; nb < 8; ++nb) {
            const int a = mb * 8 + nb;
            const int col = n0 + wn * 64 + nb * 8 + 2 * tg;
            *(__half2*)&C[(size_t)r0 * HEDIM + col] =
                __floats2half2_rn(acc[a][0] * scale, acc[a][1] * scale);
            *(__half2*)&C[(size_t)r1 * HEDIM + col] =
                __floats2half2_rn(acc[a][2] * scale, acc[a][3] * scale);
        }
    }
}

// ---------------------------------------------------------------------------
// Output GEMM on fp16 tensor cores: out_f32[8192,128] = O_h16 @ Wu_h16.
// CTA = 64 rows x 128 cols, K=1024 in 16 double-buffered chunks of 64.
// 8 warps = 4 m-strips(16) x 2 n-halves(64).
// ---------------------------------------------------------------------------
#define GO_ASTR 144                        // 64 halves/row + 16B pad
#define GO_BSTR 272                        // 128 halves/row + 16B pad
#define GO_A0 0
#define GO_A1 (64 * GO_ASTR)               // 9216
#define GO_B0 (2 * 64 * GO_ASTR)           // 18432
#define GO_B1 (GO_B0 + 64 * GO_BSTR)       // 35840
#define GO_SMEM (GO_B1 + 64 * GO_BSTR)     // 53248 bytes

__global__ __launch_bounds__(256) void gemm_out(
    const __half* __restrict__ A, const __half* __restrict__ B,
    float* __restrict__ C) {
    extern __shared__ __align__(16) char smem[];
    const int tid = threadIdx.x;
    const int wid = tid >> 5;
    const int lane = tid & 31;
    const int g = lane >> 2, tg = lane & 3;
    const int wm = wid & 3;      // m-strip (16 rows)
    const int wn = wid >> 2;     // n-half (64 cols)
    const int m0 = blockIdx.x << 6;

    const unsigned sbase = (unsigned)__cvta_generic_to_shared(smem);
    const unsigned aApat = (wm * 16 + (lane & 15)) * GO_ASTR + (lane >> 4) * 16;
    const unsigned aBpat =
        ((lane & 7) + ((lane >> 3) & 1) * 8) * GO_BSTR + wn * 128 + (lane >> 4) * 16;
    const unsigned aA[2] = {sbase + GO_A0 + aApat, sbase + GO_A1 + aApat};
    const unsigned aB[2] = {sbase + GO_B0 + aBpat, sbase + GO_B1 + aBpat};

    // stage chunk 0
    {
#pragma unroll
        for (int i = 0; i < 2; ++i) {
            int idx = tid + (i << 8);      // 0..511
            int r = idx >> 3, c = idx & 7;
            CPA16(sbase + GO_A0 + r * GO_ASTR + c * 16,
                  A + (size_t)(m0 + r) * HEDIM + c * 8);
        }
#pragma unroll
        for (int i = 0; i < 4; ++i) {
            int idx = tid + (i << 8);      // 0..1023
            int r = idx >> 4, c = idx & 15;
            CPA16(sbase + GO_B0 + r * GO_BSTR + c * 16,
                  B + (size_t)r * EDIM + c * 8);
        }
        CP_COMMIT();
    }

    float acc[8][4];
#pragma unroll
    for (int i = 0; i < 8; ++i)
#pragma unroll
        for (int j = 0; j < 4; ++j) acc[i][j] = 0.f;

    for (int ch = 0; ch < 16; ++ch) {
        const int buf = ch & 1;
        if (ch + 1 < 16) {   // prefetch chunk ch+1
            const unsigned dA = sbase + (buf ? GO_A0 : GO_A1);
            const unsigned dB = sbase + (buf ? GO_B0 : GO_B1);
            const int k1 = (ch + 1) * 64;
#pragma unroll
            for (int i = 0; i < 2; ++i) {
                int idx = tid + (i << 8);
                int r = idx >> 3, c = idx & 7;
                CPA16(dA + r * GO_ASTR + c * 16,
                      A + (size_t)(m0 + r) * HEDIM + k1 + c * 8);
            }
#pragma unroll
            for (int i = 0; i < 4; ++i) {
                int idx = tid + (i << 8);
                int r = idx >> 4, c = idx & 15;
                CPA16(dB + r * GO_BSTR + c * 16,
                      B + (size_t)(k1 + r) * EDIM + c * 8);
            }
            CP_COMMIT();
            CP_WAIT1();
        } else {
            CP_WAIT0();
        }
        __syncthreads();

#pragma unroll
        for (int ks = 0; ks < 4; ++ks) {
            unsigned a0, a1, a2, a3;
            LDSM4(a0, a1, a2, a3, aA[buf] + ks * 32);
            unsigned av = aB[buf] + ks * 16 * GO_BSTR;
#pragma unroll
            for (int np = 0; np < 4; ++np) {
                unsigned v0, v1, v2, v3;
                LDSM4T(v0, v1, v2, v3, av);
                av += 32;
                MMA16816(acc[np * 2 + 0], a0, a1, a2, a3, v0, v1);
                MMA16816(acc[np * 2 + 1], a0, a1, a2, a3, v2, v3);
            }
        }
        __syncthreads();
    }

    const int r0 = m0 + wm * 16 + g;
    const int r1 = r0 + 8;
#pragma unroll
    for (int nb = 0; nb < 8; ++nb) {
        const int col = wn * 64 + nb * 8 + 2 * tg;
        *(float2*)&C[(size_t)r0 * EDIM + col] = make_float2(acc[nb][0], acc[nb][1]);
        *(float2*)&C[(size_t)r1 * EDIM + col] = make_float2(acc[nb][2], acc[nb][3]);
    }
}

// ---------------------------------------------------------------------------
// Flash attention (R8 config): FA2 layout, 4 warps x 16 full rows,
// register-P, warp-local softmax, K AND V double-buffered, persistent Q
// fragments, 2 CTAs/SM. O written as fp16. Exact rescale-skip added.
// ---------------------------------------------------------------------------
#define BM 64
#define BN 64
#define NT (TS / BN)
#define STRH 136
#define STRB 272

#define HOFF_Q  0
#define HOFF_K0 (HOFF_Q  + BM * STRH)
#define HOFF_V0 (HOFF_K0 + BN * STRH)
#define HOFF_K1 (HOFF_V0 + BN * STRH)
#define HOFF_V1 (HOFF_K1 + BN * STRH)
#define HOFF_END (HOFF_V1 + BN * STRH)
#define SM_BYTES (HOFF_END * 2)         // 87040

__global__ __launch_bounds__(128, 2) void flash_attn_fa2(
    const __half* __restrict__ Qg, const __half* __restrict__ Kg,
    const __half* __restrict__ Vg, __half* __restrict__ Og) {
    extern __shared__ __align__(16) char smem[];

    const int tid = threadIdx.x;
    const int wid = tid >> 5;
    const int lane = tid & 31;
    const int g = lane >> 2;
    const int tg = lane & 3;

    const int h = blockIdx.y, b = blockIdx.z;
    const int q0 = blockIdx.x * BM;

    const size_t bh_off = (size_t)b * TS * HEDIM + (size_t)h * EDIM;
    const __half* Qbh = Qg + bh_off;
    const __half* Kbh = Kg + bh_off;
    const __half* Vbh = Vg + bh_off;
    __half* Obh = Og + bh_off;

    const unsigned sbase = (unsigned)__cvta_generic_to_shared(smem);
    const unsigned aQ0 = sbase + HOFF_Q * 2 +
        (wid * 16 + (lane & 15)) * STRB + (lane >> 4) * 16;
    const unsigned kpat =
        ((lane & 7) + ((lane >> 4) & 1) * 8) * STRB + ((lane >> 3) & 1) * 16;
    const unsigned vpat =
        ((lane & 7) + ((lane >> 3) & 1) * 8) * STRB + (lane >> 4) * 16;
    const unsigned aK[2] = {sbase + HOFF_K0 * 2 + kpat,
                            sbase + HOFF_K1 * 2 + kpat};
    const unsigned aV[2] = {sbase + HOFF_V0 * 2 + vpat,
                            sbase + HOFF_V1 * 2 + vpat};

    // ---- group 0: Q tile + KV tile 0 ----
    {
        const unsigned dQ = sbase + HOFF_Q * 2;
        const unsigned dK = sbase + HOFF_K0 * 2;
        const unsigned dV = sbase + HOFF_V0 * 2;
#pragma unroll
        for (int i = 0; i < 8; ++i) {
            int idx = tid + (i << 7);
            int r = idx >> 4, c = idx & 15;
            const size_t goff = (size_t)r * HEDIM + c * 8;
            const unsigned soff = r * STRB + c * 16;
            CPA16(dQ + soff, Qbh + (size_t)q0 * HEDIM + goff);
            CPA16(dK + soff, Kbh + goff);
            CPA16(dV + soff, Vbh + goff);
        }
        CP_COMMIT();
    }

    const int row0 = wid * 16 + g;
    const int row1 = row0 + 8;

    float m0 = -INFINITY, m1 = -INFINITY, l0s = 0.f, l1s = 0.f;
    float o[16][4];
#pragma unroll
    for (int nb = 0; nb < 16; ++nb)
#pragma unroll
        for (int j = 0; j < 4; ++j) o[nb][j] = 0.f;

    unsigned qf[8][4];

    for (int n = 0; n < NT; ++n) {
        const int buf = n & 1;
        if (n + 1 < NT) {
            const unsigned dK = sbase + (buf ? HOFF_K0 : HOFF_K1) * 2;
            const unsigned dV = sbase + (buf ? HOFF_V0 : HOFF_V1) * 2;
            const size_t kvg = (size_t)(n + 1) * BN * HEDIM;
#pragma unroll
            for (int i = 0; i < 8; ++i) {
                int idx = tid + (i << 7);
                int r = idx >> 4, c = idx & 15;
                const size_t goff = kvg + (size_t)r * HEDIM + c * 8;
                const unsigned soff = r * STRB + c * 16;
                CPA16(dK + soff, Kbh + goff);
                CPA16(dV + soff, Vbh + goff);
            }
            CP_COMMIT();
            CP_WAIT1();
        } else {
            CP_WAIT0();
        }
        __syncthreads();

        if (n == 0) {
#pragma unroll
            for (int ks = 0; ks < 8; ++ks)
                LDSM4(qf[ks][0], qf[ks][1], qf[ks][2], qf[ks][3],
                      aQ0 + ks * 32);
        }

        // ---- S = Q @ K^T ----
        float s[8][4];
#pragma unroll
        for (int nb = 0; nb < 8; ++nb)
#pragma unroll
            for (int j = 0; j < 4; ++j) s[nb][j] = 0.f;

        unsigned ak = aK[buf];
#pragma unroll
        for (int ks = 0; ks < 8; ++ks) {
#pragma unroll
            for (int nb2 = 0; nb2 < 4; ++nb2) {
                unsigned b0, b1, b2, b3;
                LDSM4(b0, b1, b2, b3, ak + nb2 * 16 * STRB);
                MMA16816(s[nb2 * 2 + 0], qf[ks][0], qf[ks][1], qf[ks][2],
                         qf[ks][3], b0, b1);
                MMA16816(s[nb2 * 2 + 1], qf[ks][0], qf[ks][1], qf[ks][2],
                         qf[ks][3], b2, b3);
            }
            ak += 32;
        }

        // ---- warp-local online softmax (base-2) ----
        float mx0 = -INFINITY, mx1 = -INFINITY;
#pragma unroll
        for (int nb = 0; nb < 8; ++nb) {
            mx0 = fmaxf(mx0, fmaxf(s[nb][0], s[nb][1]));
            mx1 = fmaxf(mx1, fmaxf(s[nb][2], s[nb][3]));
        }
        mx0 = fmaxf(mx0, __shfl_xor_sync(0xffffffffu, mx0, 1));
        mx0 = fmaxf(mx0, __shfl_xor_sync(0xffffffffu, mx0, 2));
        mx1 = fmaxf(mx1, __shfl_xor_sync(0xffffffffu, mx1, 1));
        mx1 = fmaxf(mx1, __shfl_xor_sync(0xffffffffu, mx1, 2));
        const float mn0 = fmaxf(m0, mx0), mn1 = fmaxf(m1, mx1);
        const float al0 = ex2f(m0 - mn0), al1 = ex2f(m1 - mn1);
        m0 = mn0; m1 = mn1;

        float ps0 = 0.f, ps1 = 0.f;
        unsigned ph[8][2];
#pragma unroll
        for (int nb = 0; nb < 8; ++nb) {
            s[nb][0] = ex2f(s[nb][0] - mn0);
            s[nb][1] = ex2f(s[nb][1] - mn0);
            s[nb][2] = ex2f(s[nb][2] - mn1);
            s[nb][3] = ex2f(s[nb][3] - mn1);
            ps0 += s[nb][0] + s[nb][1];
            ps1 += s[nb][2] + s[nb][3];
            ph[nb][0] = packh2(s[nb][0], s[nb][1]);
            ph[nb][1] = packh2(s[nb][2], s[nb][3]);
        }
        ps0 += __shfl_xor_sync(0xffffffffu, ps0, 1);
        ps0 += __shfl_xor_sync(0xffffffffu, ps0, 2);
        ps1 += __shfl_xor_sync(0xffffffffu, ps1, 1);
        ps1 += __shfl_xor_sync(0xffffffffu, ps1, 2);
        l0s = l0s * al0 + ps0;
        l1s = l1s * al1 + ps1;

        // rescale O only if some row max moved (al==1.0 exact => identity)
        if (__any_sync(0xffffffffu, (al0 != 1.f) || (al1 != 1.f))) {
#pragma unroll
            for (int nb = 0; nb < 16; ++nb) {
                o[nb][0] *= al0; o[nb][1] *= al0;
                o[nb][2] *= al1; o[nb][3] *= al1;
            }
        }

        // ---- O += P @ V ----
        unsigned av0 = aV[buf];
#pragma unroll
        for (int ks = 0; ks < 4; ++ks) {
            const unsigned pa0 = ph[2 * ks][0], pa1 = ph[2 * ks][1];
            const unsigned pa2 = ph[2 * ks + 1][0], pa3 = ph[2 * ks + 1][1];
            unsigned av = av0;
#pragma unroll
            for (int np = 0; np < 8; ++np) {
                unsigned v0, v1, v2, v3;
                LDSM4T(v0, v1, v2, v3, av);
                MMA16816(o[np * 2 + 0], pa0, pa1, pa2, pa3, v0, v1);
                MMA16816(o[np * 2 + 1], pa0, pa1, pa2, pa3, v2, v3);
                av += 32;
            }
            av0 += 16 * STRB;
        }
        __syncthreads();
    }

    // ---- normalize + write O (fp16) ----
    const float inv0 = 1.f / l0s, inv1 = 1.f / l1s;
#pragma unroll
    for (int nb = 0; nb < 16; ++nb) {
        const int col = nb * 8 + 2 * tg;
        *(unsigned*)&Obh[(size_t)(q0 + row0) * HEDIM + col] =
            packh2(o[nb][0] * inv0, o[nb][1] * inv0);
        *(unsigned*)&Obh[(size_t)(q0 + row1) * HEDIM + col] =
            packh2(o[nb][2] * inv1, o[nb][3] * inv1);
    }
}

// ---------------------------------------------------------------------------
extern "C" void kernel_launch(void* const* d_in, const int* in_sizes, int n_in,
                              void* d_out, int out_size) {
    (void)in_sizes; (void)n_in; (void)out_size;
    const float* k  = (const float*)d_in[0];
    const float* q  = (const float*)d_in[1];
    const float* v  = (const float*)d_in[2];
    const float* Wk = (const float*)d_in[3];
    const float* Wq = (const float*)d_in[4];
    const float* Wv = (const float*)d_in[5];
    const float* Wu = (const float*)d_in[6];
    float* out = (float*)d_out;

    __half *gQ, *gK, *gV, *gO, *gWu;
    cudaGetSymbolAddress((void**)&gQ, g_Qh);
    cudaGetSymbolAddress((void**)&gK, g_Kh);
    cudaGetSymbolAddress((void**)&gV, g_Vh);
    cudaGetSymbolAddress((void**)&gO, g_Oh);
    cudaGetSymbolAddress((void**)&gWu, g_Wuh);

    cudaFuncSetAttribute(flash_attn_fa2,
                         cudaFuncAttributeMaxDynamicSharedMemorySize, SM_BYTES);
    cudaFuncSetAttribute(gemm_proj,
                         cudaFuncAttributeMaxDynamicSharedMemorySize, GP_SMEM);
    cudaFuncSetAttribute(gemm_out,
                         cudaFuncAttributeMaxDynamicSharedMemorySize, GO_SMEM);

    const float qscale = 0.12751744f;  // log2(e)/sqrt(128)
    dim3 blk(256);

    wu_to_h<<<HEDIM * EDIM / 1024, blk>>>(Wu, gWu);

    dim3 gproj(HEDIM / 128, BT / 128);
    gemm_proj<<<gproj, blk, GP_SMEM>>>(q, Wq, gQ, qscale);
    gemm_proj<<<gproj, blk, GP_SMEM>>>(k, Wk, gK, 1.0f);
    gemm_proj<<<gproj, blk, GP_SMEM>>>(v, Wv, gV, 1.0f);

    dim3 gatt(TS / BM, NH, NB);
    flash_attn_fa2<<<gatt, dim3(128), SM_BYTES>>>(gQ, gK, gV, gO);

    gemm_out<<<BT / 64, blk, GO_SMEM>>>(gO, gWu, out);
}